// round 17
// baseline (speedup 1.0000x reference)
#include <cuda_runtime.h>
#include <cstdint>

// Problem constants (fixed by the reference: B=2, G=64)
constexpr int G3      = 64 * 64 * 64;   // 262144 voxels per batch
constexpr int NB      = 2;
constexpr int THREADS = 192;            // 64 pairs x 3 j-roles
constexpr int PAIRS_PER_CTA = 64;
constexpr int NPAIRS  = NB * G3 / 2;    // 262144 voxel pairs

// Packed f32x2 ops (PTX-only; ptxas never auto-fuses FFMA2 from C++).
__device__ __forceinline__ uint64_t fma2(uint64_t a, uint64_t b, uint64_t c) {
    uint64_t d;
    asm("fma.rn.f32x2 %0, %1, %2, %3;" : "=l"(d) : "l"(a), "l"(b), "l"(c));
    return d;
}
__device__ __forceinline__ uint64_t mul2(uint64_t a, uint64_t b) {
    uint64_t d;
    asm("mul.rn.f32x2 %0, %1, %2;" : "=l"(d) : "l"(a), "l"(b));
    return d;
}
// Un-hoistable shared load for C0 (volatile is load-bearing: plain loads let
// ptxas hoist the loop-invariant C0 words into registers -> spills; R6/R8).
__device__ __forceinline__ uint64_t lds64(uint32_t saddr) {
    uint64_t d;
    asm volatile("ld.shared.b64 %0, [%1];" : "=l"(d) : "r"(saddr));
    return d;
}
__device__ __forceinline__ uint32_t smem_u32(const void* p) {
    uint32_t r;
    asm("{ .reg .u64 t; cvta.to.shared.u64 t, %1; cvt.u32.u64 %0, t; }"
        : "=r"(r) : "l"(p));
    return r;
}

// C_ijkl[b,v] = sum_{mnop} a[b,m,i,v] a[b,n,j,v] a[b,o,k,v] a[b,p,l,v] C0[mnop]
//
// Cooperative 3-thread teams per voxel pair: thread (pr, j) computes, for each
// i, one third of T1 (9 entries) into shared memory, then after a barrier
// consumes ALL of T1 from smem for its own j (stages 2-4). T1 never lives in
// registers, cutting the per-thread live set from ~96 data regs (which pinned
// every previous variant at 16 warps/SM) to ~45 -> 4 CTAs x 6 warps = 24
// warps/SM. No FMA work is duplicated (stage 1 is split, not replicated).
__global__ __launch_bounds__(THREADS, 4)
void alphaC0_42C_kernel(const float* __restrict__ a,
                        const float* __restrict__ c0,
                        float* __restrict__ out)
{
    // sc0[m*27+nop] splatted to both f32x2 lanes (direct FFMA2 operand).
    __shared__ uint64_t sc0[81];
    // T1 exchange: [entry][pair] so STS/LDS are lane-consecutive (no conflicts).
    __shared__ uint64_t T1s[27][PAIRS_PER_CTA];

    const int tid = threadIdx.x;
    const int j   = tid >> 6;        // 0..2  (warps 0-1: j=0, 2-3: j=1, 4-5: j=2)
    const int pr  = tid & 63;        // pair slot within CTA

    if (tid < 81) {
        float c = c0[tid];
        float2 cc = make_float2(c, c);
        sc0[tid] = *reinterpret_cast<uint64_t*>(&cc);
    }
    __syncthreads();
    const uint32_t sbase = smem_u32(sc0);

    // CTA covers 64 consecutive pairs (128 voxels); G3 % 128 == 0 -> no CTA
    // straddles the batch boundary.
    const uint32_t pair = (uint32_t)blockIdx.x * PAIRS_PER_CTA + pr;
    const uint32_t v2   = pair * 2;
    const int      b    = (v2 >= (uint32_t)G3) ? 1 : 0;
    const uint32_t v    = v2 - (uint32_t)b * G3;

    // Full 3x3 per-voxel matrix for both voxels of the pair (all of A is
    // needed in stages 2-4 regardless of j).
    const float* ab = a + (long)b * 9 * G3 + v;
    uint64_t A[9];
#pragma unroll
    for (int mi = 0; mi < 9; ++mi)
        A[mi] = *reinterpret_cast<const uint64_t*>(ab + (uint32_t)(mi * G3));

    const uint64_t Aj0 = A[0 * 3 + j], Aj1 = A[1 * 3 + j], Aj2 = A[2 * 3 + j];
    float* ob = out + (long)b * 81 * G3 + v;

#pragma unroll 1
    for (int i = 0; i < 3; ++i) {
        const uint64_t Ai0 = A[0 * 3 + i], Ai1 = A[1 * 3 + i], Ai2 = A[2 * 3 + i];

        __syncthreads();   // T1s from iteration i-1 fully consumed

        // Stage 1 (split): this thread computes T1 entries [j*9, j*9+9).
        // sc0 addresses are warp-uniform -> broadcast LDS.
#pragma unroll
        for (int e = 0; e < 9; ++e) {
            const int nop = j * 9 + e;
            uint64_t s = mul2(Ai0, lds64(sbase + (uint32_t)(nop * 8)));
            s = fma2(Ai1, lds64(sbase + (uint32_t)((27 + nop) * 8)), s);
            s = fma2(Ai2, lds64(sbase + (uint32_t)((54 + nop) * 8)), s);
            T1s[nop][pr] = s;
        }
        __syncthreads();   // all 27 T1 entries visible

        // Stage 2: T2[o,p] = sum_n A[n,j] * T1[n,o,p]  (T1 straight from smem)
        uint64_t T2[9];
#pragma unroll
        for (int op = 0; op < 9; ++op) {
            uint64_t s = mul2(Aj0, T1s[op][pr]);
            s = fma2(Aj1, T1s[9 + op][pr], s);
            s = fma2(Aj2, T1s[18 + op][pr], s);
            T2[op] = s;
        }

        // Output plane base for (i, j).
        float* obij = ob + (uint32_t)((i * 3 + j) * 9 * G3);
#pragma unroll
        for (int k = 0; k < 3; ++k) {
            // Stage 3: T3[p] = sum_o A[o,k] * T2[o,p]
            uint64_t T3[3];
#pragma unroll
            for (int p = 0; p < 3; ++p) {
                uint64_t s = mul2(A[0 * 3 + k], T2[p]);
                s = fma2(A[1 * 3 + k], T2[3 + p], s);
                s = fma2(A[2 * 3 + k], T2[6 + p], s);
                T3[p] = s;
            }
#pragma unroll
            for (int l = 0; l < 3; ++l) {
                // Stage 4: C[i,j,k,l] = sum_p A[p,l] * T3[p]
                uint64_t r = mul2(A[0 * 3 + l], T3[0]);
                r = fma2(A[1 * 3 + l], T3[1], r);
                r = fma2(A[2 * 3 + l], T3[2], r);
                // Warp = one j x 32 consecutive pairs -> 256 B coalesced.
                *reinterpret_cast<uint64_t*>(
                    obij + (uint32_t)((k * 3 + l) * G3)) = r;
            }
        }
    }
}

extern "C" void kernel_launch(void* const* d_in, const int* in_sizes, int n_in,
                              void* d_out, int out_size)
{
    const float* a   = (const float*)d_in[0];   // alphatensor (2,3,3,64,64,64)
    const float* c0  = (const float*)d_in[1];   // C0_4 (3,3,3,3)
    float*       out = (float*)d_out;           // (2,3,3,3,3,64,64,64)

    const int blocks = NPAIRS / PAIRS_PER_CTA;  // 4096
    alphaC0_42C_kernel<<<blocks, THREADS>>>(a, c0, out);
}